// round 11
// baseline (speedup 1.0000x reference)
#include <cuda_runtime.h>
#include <cuda_bf16.h>
#include <cuda_fp16.h>
#include <cstdint>

#define D 128
#define EPS 1e-5f
#define MAXN 100000
#define MAXE 1600000
#define SA 136
#define SA_W (SA / 2)

__device__ __half g_Z[12800000];       // N x D fp16 (GEMM out / SpMM in)
__device__ __half g_A[12800000];       // N x D fp16 (SpMM out / stats + GEMM in)
__device__ float g_stats[4 * D];       // layer0: [0:256), layer1: [256:512)
__device__ int   g_deg[MAXN];
__device__ int   g_rowptr[MAXN + 1];
__device__ int   g_cursor[MAXN];
__device__ int2  g_edata[MAXE];
__device__ int   g_blksum[1024];
__device__ __nv_bfloat16 g_Whi[3 * 128 * SA];
__device__ __nv_bfloat16 g_Wlo[3 * 128 * SA];

// ---------------- prep: W transpose/split only (main stream) ----------------
__global__ void prep_kernel(const float* __restrict__ W0, const float* __restrict__ W1,
                            const float* __restrict__ W2,
                            __nv_bfloat16* __restrict__ whi, __nv_bfloat16* __restrict__ wlo)
{
    const float* W = (blockIdx.x == 0) ? W0 : (blockIdx.x == 1) ? W1 : W2;
    __nv_bfloat16* hi = whi + blockIdx.x * 128 * SA;
    __nv_bfloat16* lo = wlo + blockIdx.x * 128 * SA;
    for (int idx = threadIdx.x; idx < 16384; idx += blockDim.x) {
        int k = idx >> 7, n = idx & 127;     // W[k][n] -> Wt[n][k]
        float w = W[idx];
        __nv_bfloat16 h = __float2bfloat16(w);
        __nv_bfloat16 l = __float2bfloat16(w - __bfloat162float(h));
        hi[n * SA + k] = h;
        lo[n * SA + k] = l;
    }
}

// ---------------- init: zero deg + BOTH stats buffers (side stream) ----------------
__global__ void init_kernel(int* __restrict__ deg, float* __restrict__ stats, int N)
{
    int b = blockIdx.x;
    if (b == 12) {
        // 512 entries, 256 threads: two each (R9 lesson)
        stats[threadIdx.x]       = 0.f;
        stats[threadIdx.x + 256] = 0.f;
    } else {
        int per = (N + 11) / 12;
        int beg = b * per;
        int end = min(beg + per, N);
        for (int i = beg + (int)threadIdx.x; i < end; i += blockDim.x) deg[i] = 0;
    }
}

// ---------------- HMMA GEMM with fused BN finalize + act ----------------
// H is fp32 (layer 0) or fp16 (layers 1/2) selected by h16 flag.
#define SM_AHI 0
#define SM_ALO 17408
#define SM_WHI 34816
#define SM_WLO 69632
#define SM_BN  104448
#define SM_TOT (104448 + 1024)

__device__ __forceinline__ void mma_bf16(float* c, uint32_t a0, uint32_t a1,
                                         uint32_t a2, uint32_t a3,
                                         uint32_t b0, uint32_t b1)
{
    asm volatile(
        "mma.sync.aligned.m16n8k16.row.col.f32.bf16.bf16.f32 "
        "{%0,%1,%2,%3}, {%4,%5,%6,%7}, {%8,%9}, {%0,%1,%2,%3};"
        : "+f"(c[0]), "+f"(c[1]), "+f"(c[2]), "+f"(c[3])
        : "r"(a0), "r"(a1), "r"(a2), "r"(a3), "r"(b0), "r"(b1));
}

__global__ __launch_bounds__(256) void gemm_mma_kernel(
    const void* __restrict__ Hp, int h16,
    const __nv_bfloat16* __restrict__ whi, const __nv_bfloat16* __restrict__ wlo,
    const float* __restrict__ bias,
    const float* __restrict__ stats,
    const float* __restrict__ gam, const float* __restrict__ bet,
    __half* __restrict__ out, int N, int use_act, float invN)
{
    extern __shared__ char sm[];
    int tid = threadIdx.x, wid = tid >> 5, lane = tid & 31;

    float* sScale = (float*)(sm + SM_BN);
    float* sShift = sScale + 128;

    // fused BN finalize: per-block scale/shift from raw stats
    if (use_act && tid < 128) {
        float m = stats[tid] * invN;
        float v = stats[128 + tid] * invN - m * m;
        float sc = gam[tid] * rsqrtf(v + EPS);
        sScale[tid] = sc;
        sShift[tid] = bet[tid] - m * sc;
    }

    // stage W hi/lo (straight copy, already padded/transposed)
    {
        const float4* bh = (const float4*)whi;
        const float4* bl = (const float4*)wlo;
        float4* sh = (float4*)(sm + SM_WHI);
        float4* sl = (float4*)(sm + SM_WLO);
#pragma unroll
        for (int i = 0; i < 9; i++) {
            int idx = tid + 256 * i;
            if (idx < 2176) { sh[idx] = bh[idx]; sl[idx] = bl[idx]; }
        }
    }
    __syncthreads();   // sScale/sShift ready before A staging

    // stage A tile: load H rows (fp32 or fp16), act, bf16 split, padded store
    int row0 = blockIdx.x * 64;
    {
        const float4* Hf = (const float4*)Hp + (size_t)row0 * 32;
        const uint2*  Hh = (const uint2*)Hp + (size_t)row0 * 32;
#pragma unroll
        for (int i = 0; i < 8; i++) {
            int idx = tid + 256 * i;          // 2048 chunks of 4 elems
            int r = idx >> 5;
            int c = (idx & 31) * 4;
            float4 v;
            if (row0 + r < N) {
                if (h16) {
                    uint2 pv = Hh[idx];
                    float2 a01 = __half22float2(*(__half2*)&pv.x);
                    float2 a23 = __half22float2(*(__half2*)&pv.y);
                    v = make_float4(a01.x, a01.y, a23.x, a23.y);
                } else {
                    v = Hf[idx];
                }
            } else v = make_float4(0.f, 0.f, 0.f, 0.f);
            if (use_act) {
                float4 sc = *(const float4*)(sScale + c);
                float4 sf = *(const float4*)(sShift + c);
                v.x = fmaxf(fmaf(v.x, sc.x, sf.x), 0.f);
                v.y = fmaxf(fmaf(v.y, sc.y, sf.y), 0.f);
                v.z = fmaxf(fmaf(v.z, sc.z, sf.z), 0.f);
                v.w = fmaxf(fmaf(v.w, sc.w, sf.w), 0.f);
            }
            __nv_bfloat162 h01 = __floats2bfloat162_rn(v.x, v.y);
            __nv_bfloat162 h23 = __floats2bfloat162_rn(v.z, v.w);
            float2 hf01 = __bfloat1622float2(h01);
            float2 hf23 = __bfloat1622float2(h23);
            __nv_bfloat162 l01 = __floats2bfloat162_rn(v.x - hf01.x, v.y - hf01.y);
            __nv_bfloat162 l23 = __floats2bfloat162_rn(v.z - hf23.x, v.w - hf23.y);
            uint32_t w0 = (uint32_t)(r * SA_W + (c >> 1));
            uint2 hh; hh.x = *(uint32_t*)&h01; hh.y = *(uint32_t*)&h23;
            uint2 ll; ll.x = *(uint32_t*)&l01; ll.y = *(uint32_t*)&l23;
            *(uint2*)(sm + SM_AHI + w0 * 4) = hh;
            *(uint2*)(sm + SM_ALO + w0 * 4) = ll;
        }
    }
    __syncthreads();

    const uint32_t* pAh = (const uint32_t*)(sm + SM_AHI);
    const uint32_t* pAl = (const uint32_t*)(sm + SM_ALO);
    const uint32_t* pBh = (const uint32_t*)(sm + SM_WHI);
    const uint32_t* pBl = (const uint32_t*)(sm + SM_WLO);

    int m0 = (wid & 3) * 16;
    int n0 = (wid >> 2) * 64;
    int gg = lane >> 2, q = lane & 3;

    float acc[8][4] = {};
#pragma unroll
    for (int k = 0; k < 8; k++) {
        int kb2 = k * 8;
        int ai = (m0 + gg) * SA_W + kb2 + q;
        uint32_t ah0 = pAh[ai],     ah1 = pAh[ai + 8 * SA_W];
        uint32_t ah2 = pAh[ai + 4], ah3 = pAh[ai + 8 * SA_W + 4];
        uint32_t al0 = pAl[ai],     al1 = pAl[ai + 8 * SA_W];
        uint32_t al2 = pAl[ai + 4], al3 = pAl[ai + 8 * SA_W + 4];
#pragma unroll
        for (int t = 0; t < 8; t++) {
            int bi = (n0 + t * 8 + gg) * SA_W + kb2 + q;
            uint32_t bh0 = pBh[bi], bh1 = pBh[bi + 4];
            uint32_t bl0 = pBl[bi], bl1 = pBl[bi + 4];
            mma_bf16(acc[t], ah0, ah1, ah2, ah3, bh0, bh1);
            mma_bf16(acc[t], al0, al1, al2, al3, bh0, bh1);
            mma_bf16(acc[t], ah0, ah1, ah2, ah3, bl0, bl1);
        }
    }

    int r0g = row0 + m0 + gg;
#pragma unroll
    for (int t = 0; t < 8; t++) {
        int colp = n0 + t * 8 + q * 2;
        float2 bv = *(const float2*)(bias + colp);
        if (r0g < N) {
            __half2 o = __floats2half2_rn(acc[t][0] + bv.x, acc[t][1] + bv.y);
            *(__half2*)(out + (size_t)r0g * D + colp) = o;
        }
        if (r0g + 8 < N) {
            __half2 o = __floats2half2_rn(acc[t][2] + bv.x, acc[t][3] + bv.y);
            *(__half2*)(out + (size_t)(r0g + 8) * D + colp) = o;
        }
    }
}

// ---------------- CSR build ----------------
__global__ void hist_kernel(const int* __restrict__ row, int* __restrict__ deg, int E)
{
    int e = blockIdx.x * blockDim.x + threadIdx.x;
    if (e < E) atomicAdd(&deg[row[e]], 1);
}

__global__ __launch_bounds__(1024) void blocksum_kernel(
    const int* __restrict__ deg, int* __restrict__ blksum, int N)
{
    int i = blockIdx.x * 1024 + threadIdx.x;
    int v = (i < N) ? deg[i] : 0;
#pragma unroll
    for (int off = 16; off > 0; off >>= 1) v += __shfl_down_sync(0xffffffffu, v, off);
    __shared__ int smr[32];
    int lane = threadIdx.x & 31, wid = threadIdx.x >> 5;
    if (lane == 0) smr[wid] = v;
    __syncthreads();
    if (wid == 0) {
        v = smr[lane];
#pragma unroll
        for (int off = 16; off > 0; off >>= 1) v += __shfl_down_sync(0xffffffffu, v, off);
        if (lane == 0) blksum[blockIdx.x] = v;
    }
}

__global__ __launch_bounds__(1024) void scanpart_kernel(int* __restrict__ blksum, int nb)
{
    __shared__ int smr[1024];
    int tid = threadIdx.x;
    smr[tid] = (tid < nb) ? blksum[tid] : 0;
    __syncthreads();
    if (tid == 0) {
        int run = 0;
        for (int i = 0; i < nb; i++) { int t = smr[i]; smr[i] = run; run += t; }
    }
    __syncthreads();
    if (tid < nb) blksum[tid] = smr[tid];
}

__global__ __launch_bounds__(1024) void rowptr_kernel(
    const int* __restrict__ deg, const int* __restrict__ blksum,
    int* __restrict__ rowptr, int* __restrict__ cursor, int N)
{
    int i = blockIdx.x * 1024 + threadIdx.x;
    int v = (i < N) ? deg[i] : 0;
    int lane = threadIdx.x & 31, wid = threadIdx.x >> 5;
    int incl = v;
#pragma unroll
    for (int off = 1; off < 32; off <<= 1) {
        int t = __shfl_up_sync(0xffffffffu, incl, off);
        if (lane >= off) incl += t;
    }
    __shared__ int wsum[32];
    if (lane == 31) wsum[wid] = incl;
    __syncthreads();
    if (wid == 0) {
        int w = wsum[lane];
#pragma unroll
        for (int off = 1; off < 32; off <<= 1) {
            int t = __shfl_up_sync(0xffffffffu, w, off);
            if (lane >= off) w += t;
        }
        wsum[lane] = w;
    }
    __syncthreads();
    int offset = blksum[blockIdx.x] + (wid > 0 ? wsum[wid - 1] : 0);
    int excl = offset + incl - v;
    if (i < N) { rowptr[i] = excl; cursor[i] = excl; }
    if (i == N - 1) rowptr[N] = excl + v;
}

__global__ void scatter_kernel(
    const int* __restrict__ row, const int* __restrict__ col,
    const float* __restrict__ ew, int* __restrict__ cursor,
    int2* __restrict__ edata, int E)
{
    int e = blockIdx.x * blockDim.x + threadIdx.x;
    if (e < E) {
        int p = atomicAdd(&cursor[row[e]], 1);
        int2 ed; ed.x = col[e]; ed.y = __float_as_int(ew[e]);
        edata[p] = ed;
    }
}

// ---------------- gather SpMM (fp16 in): fp16 out (outh) or fp32 out (outf) ------
__global__ __launch_bounds__(256) void spmm_kernel(
    const __half* __restrict__ H, const int* __restrict__ rowptr,
    const int2* __restrict__ edata,
    __half* __restrict__ outh, float* __restrict__ outf, int N)
{
    int r = blockIdx.x * 8 + (threadIdx.x >> 5);
    if (r >= N) return;
    int lane = threadIdx.x & 31;
    int start = rowptr[r], end = rowptr[r + 1];

    float4 acc = make_float4(0.f, 0.f, 0.f, 0.f);
    const uint2* Hv = (const uint2*)H;

    for (int base = start; base < end; base += 32) {
        int e = base + lane;
        int c = 0, wb = 0;
        if (e < end) { int2 ed = edata[e]; c = ed.x; wb = ed.y; }
        int cnt = min(32, end - base);
#pragma unroll 4
        for (int i = 0; i < cnt; i++) {
            int ci = __shfl_sync(0xffffffffu, c, i);
            float wi = __int_as_float(__shfl_sync(0xffffffffu, wb, i));
            uint2 pv = Hv[(size_t)ci * 32 + lane];
            float2 v01 = __half22float2(*(__half2*)&pv.x);
            float2 v23 = __half22float2(*(__half2*)&pv.y);
            acc.x = fmaf(wi, v01.x, acc.x);
            acc.y = fmaf(wi, v01.y, acc.y);
            acc.z = fmaf(wi, v23.x, acc.z);
            acc.w = fmaf(wi, v23.y, acc.w);
        }
    }
    if (outh) {
        __half2 o01 = __floats2half2_rn(acc.x, acc.y);
        __half2 o23 = __floats2half2_rn(acc.z, acc.w);
        uint2 st; st.x = *(uint32_t*)&o01; st.y = *(uint32_t*)&o23;
        ((uint2*)(outh + (size_t)r * D))[lane] = st;
    } else {
        ((float4*)(outf + (size_t)r * D))[lane] = acc;
    }
}

// ---------------- BN stats (reads fp16 A) ----------------
#define RPB 256
__global__ __launch_bounds__(128) void bn_stats_kernel(
    const __half* __restrict__ A, float* __restrict__ stats, int N)
{
    int d = threadIdx.x;
    int r0 = blockIdx.x * RPB;
    int rend = min(r0 + RPB, N);
    float s = 0.f, q = 0.f;
    for (int r = r0; r < rend; r++) {
        float v = __half2float(A[(size_t)r * D + d]);
        s += v;
        q = fmaf(v, v, q);
    }
    atomicAdd(&stats[d], s);
    atomicAdd(&stats[128 + d], q);
}

// ---------------------------------------------------------------------------
extern "C" void kernel_launch(void* const* d_in, const int* in_sizes, int n_in,
                              void* d_out, int out_size)
{
    const float* x   = (const float*)d_in[0];
    const float* ew  = (const float*)d_in[1];
    const float* W0  = (const float*)d_in[2];
    const float* b0  = (const float*)d_in[3];
    const float* g0  = (const float*)d_in[4];
    const float* be0 = (const float*)d_in[5];
    const float* W1  = (const float*)d_in[6];
    const float* b1  = (const float*)d_in[7];
    const float* g1  = (const float*)d_in[8];
    const float* be1 = (const float*)d_in[9];
    const float* W2  = (const float*)d_in[10];
    const float* b2  = (const float*)d_in[11];
    const int*   row = (const int*)d_in[12];
    const int*   col = (const int*)d_in[13];
    float* out = (float*)d_out;

    int N = in_sizes[0] / D;
    int E = in_sizes[1];

    float *Stats;
    __half *Z, *A;
    int *Deg, *Rowptr, *Cursor, *Blksum;
    int2* Edata;
    __nv_bfloat16 *Whi, *Wlo;
    cudaGetSymbolAddress((void**)&Z, g_Z);
    cudaGetSymbolAddress((void**)&A, g_A);
    cudaGetSymbolAddress((void**)&Stats, g_stats);
    cudaGetSymbolAddress((void**)&Deg, g_deg);
    cudaGetSymbolAddress((void**)&Rowptr, g_rowptr);
    cudaGetSymbolAddress((void**)&Cursor, g_cursor);
    cudaGetSymbolAddress((void**)&Edata, g_edata);
    cudaGetSymbolAddress((void**)&Blksum, g_blksum);
    cudaGetSymbolAddress((void**)&Whi, g_Whi);
    cudaGetSymbolAddress((void**)&Wlo, g_Wlo);

    cudaFuncSetAttribute(gemm_mma_kernel, cudaFuncAttributeMaxDynamicSharedMemorySize, SM_TOT);

    int gemmGrid  = (N + 63) / 64;
    int spmmGrid  = (N + 7) / 8;
    int statsGrid = (N + RPB - 1) / RPB;
    int nb        = (N + 1023) / 1024;
    float invN = 1.0f / (float)N;

    // ---- fork: CSR build on side stream, overlapped with W prep + GEMM0 ----
    cudaStream_t s2;
    cudaStreamCreateWithFlags(&s2, cudaStreamNonBlocking);
    cudaEvent_t evFork, evJoin;
    cudaEventCreateWithFlags(&evFork, cudaEventDisableTiming);
    cudaEventCreateWithFlags(&evJoin, cudaEventDisableTiming);

    cudaEventRecord(evFork, 0);
    cudaStreamWaitEvent(s2, evFork, 0);
    init_kernel<<<13, 256, 0, s2>>>(Deg, Stats, N);
    hist_kernel<<<(E + 255) / 256, 256, 0, s2>>>(row, Deg, E);
    blocksum_kernel<<<nb, 1024, 0, s2>>>(Deg, Blksum, N);
    scanpart_kernel<<<1, 1024, 0, s2>>>(Blksum, nb);
    rowptr_kernel<<<nb, 1024, 0, s2>>>(Deg, Blksum, Rowptr, Cursor, N);
    scatter_kernel<<<(E + 255) / 256, 256, 0, s2>>>(row, col, ew, Cursor, Edata, E);
    cudaEventRecord(evJoin, s2);

    // main stream: W prep + GEMM0 concurrent with CSR build
    prep_kernel<<<3, 256>>>(W0, W1, W2, Whi, Wlo);
    gemm_mma_kernel<<<gemmGrid, 256, SM_TOT>>>(x, 0, Whi, Wlo, b0,
                                               nullptr, nullptr, nullptr, Z, N, 0, invN);
    cudaStreamWaitEvent(0, evJoin, 0);

    // ---- layer 0 ----
    spmm_kernel<<<spmmGrid, 256>>>(Z, Rowptr, Edata, A, nullptr, N);
    bn_stats_kernel<<<statsGrid, 128>>>(A, Stats, N);

    // ---- layer 1 (applies BN0 fused) ----
    gemm_mma_kernel<<<gemmGrid, 256, SM_TOT>>>(A, 1, Whi + 128 * SA, Wlo + 128 * SA, b1,
                                               Stats, g0, be0, Z, N, 1, invN);
    spmm_kernel<<<spmmGrid, 256>>>(Z, Rowptr, Edata, A, nullptr, N);
    bn_stats_kernel<<<statsGrid, 128>>>(A, Stats + 256, N);

    // ---- layer 2 (applies BN1 fused; fp32 output to d_out) ----
    gemm_mma_kernel<<<gemmGrid, 256, SM_TOT>>>(A, 1, Whi + 256 * SA, Wlo + 256 * SA, b2,
                                               Stats + 256, g1, be1, Z, N, 1, invN);
    spmm_kernel<<<spmmGrid, 256>>>(Z, Rowptr, Edata, nullptr, out, N);

    cudaEventDestroy(evFork);
    cudaEventDestroy(evJoin);
    cudaStreamDestroy(s2);
}

// round 12
// speedup vs baseline: 1.3763x; 1.3763x over previous
#include <cuda_runtime.h>
#include <cuda_bf16.h>
#include <cuda_fp16.h>
#include <cstdint>

#define D 128
#define EPS 1e-5f
#define MAXN 100000
#define MAXE 1600000
#define SA 136
#define SA_W (SA / 2)

__device__ __half g_Z[12800000];       // N x D fp16 (GEMM out / SpMM in)
__device__ __half g_A[12800000];       // N x D fp16 (SpMM out / stats + GEMM in)
__device__ float g_stats[4 * D];       // layer0: [0:256), layer1: [256:512)
__device__ int   g_deg[MAXN];
__device__ int   g_rowptr[MAXN + 1];
__device__ int   g_cursor[MAXN];
__device__ int2  g_edata[MAXE];
__device__ int   g_blksum[1024];
__device__ __nv_bfloat16 g_Whi[3 * 128 * SA];
__device__ __nv_bfloat16 g_Wlo[3 * 128 * SA];

// ---------------- prep: W transpose/split + zero deg + zero BOTH stats buffers ------
__global__ void prep_kernel(const float* __restrict__ W0, const float* __restrict__ W1,
                            const float* __restrict__ W2,
                            __nv_bfloat16* __restrict__ whi, __nv_bfloat16* __restrict__ wlo,
                            int* __restrict__ deg, float* __restrict__ stats, int N)
{
    int b = blockIdx.x;
    if (b < 3) {
        const float* W = (b == 0) ? W0 : (b == 1) ? W1 : W2;
        __nv_bfloat16* hi = whi + b * 128 * SA;
        __nv_bfloat16* lo = wlo + b * 128 * SA;
        for (int idx = threadIdx.x; idx < 16384; idx += blockDim.x) {
            int k = idx >> 7, n = idx & 127;     // W[k][n] -> Wt[n][k]
            float w = W[idx];
            __nv_bfloat16 h = __float2bfloat16(w);
            __nv_bfloat16 l = __float2bfloat16(w - __bfloat162float(h));
            hi[n * SA + k] = h;
            lo[n * SA + k] = l;
        }
    } else if (b == 3) {
        // 512 entries, 256 threads: two each (R9 lesson)
        stats[threadIdx.x]       = 0.f;
        stats[threadIdx.x + 256] = 0.f;
    } else {
        int per = (N + 11) / 12;
        int beg = (b - 4) * per;
        int end = min(beg + per, N);
        for (int i = beg + (int)threadIdx.x; i < end; i += blockDim.x) deg[i] = 0;
    }
}

// ---------------- HMMA GEMM with fused BN finalize + act ----------------
// H is fp32 (layer 0) or fp16 (layers 1/2) selected by h16 flag.
#define SM_AHI 0
#define SM_ALO 17408
#define SM_WHI 34816
#define SM_WLO 69632
#define SM_BN  104448
#define SM_TOT (104448 + 1024)

__device__ __forceinline__ void mma_bf16(float* c, uint32_t a0, uint32_t a1,
                                         uint32_t a2, uint32_t a3,
                                         uint32_t b0, uint32_t b1)
{
    asm volatile(
        "mma.sync.aligned.m16n8k16.row.col.f32.bf16.bf16.f32 "
        "{%0,%1,%2,%3}, {%4,%5,%6,%7}, {%8,%9}, {%0,%1,%2,%3};"
        : "+f"(c[0]), "+f"(c[1]), "+f"(c[2]), "+f"(c[3])
        : "r"(a0), "r"(a1), "r"(a2), "r"(a3), "r"(b0), "r"(b1));
}

__global__ __launch_bounds__(256) void gemm_mma_kernel(
    const void* __restrict__ Hp, int h16,
    const __nv_bfloat16* __restrict__ whi, const __nv_bfloat16* __restrict__ wlo,
    const float* __restrict__ bias,
    const float* __restrict__ stats,
    const float* __restrict__ gam, const float* __restrict__ bet,
    __half* __restrict__ out, int N, int use_act, float invN)
{
    extern __shared__ char sm[];
    int tid = threadIdx.x, wid = tid >> 5, lane = tid & 31;

    float* sScale = (float*)(sm + SM_BN);
    float* sShift = sScale + 128;

    // fused BN finalize: per-block scale/shift from raw stats
    if (use_act && tid < 128) {
        float m = stats[tid] * invN;
        float v = stats[128 + tid] * invN - m * m;
        float sc = gam[tid] * rsqrtf(v + EPS);
        sScale[tid] = sc;
        sShift[tid] = bet[tid] - m * sc;
    }

    // stage W hi/lo (straight copy, already padded/transposed)
    {
        const float4* bh = (const float4*)whi;
        const float4* bl = (const float4*)wlo;
        float4* sh = (float4*)(sm + SM_WHI);
        float4* sl = (float4*)(sm + SM_WLO);
#pragma unroll
        for (int i = 0; i < 9; i++) {
            int idx = tid + 256 * i;
            if (idx < 2176) { sh[idx] = bh[idx]; sl[idx] = bl[idx]; }
        }
    }
    __syncthreads();   // sScale/sShift ready before A staging

    // stage A tile: load H rows (fp32 or fp16), act, bf16 split, padded store
    int row0 = blockIdx.x * 64;
    {
        const float4* Hf = (const float4*)Hp + (size_t)row0 * 32;
        const uint2*  Hh = (const uint2*)Hp + (size_t)row0 * 32;
#pragma unroll
        for (int i = 0; i < 8; i++) {
            int idx = tid + 256 * i;          // 2048 chunks of 4 elems
            int r = idx >> 5;
            int c = (idx & 31) * 4;
            float4 v;
            if (row0 + r < N) {
                if (h16) {
                    uint2 pv = Hh[idx];
                    float2 a01 = __half22float2(*(__half2*)&pv.x);
                    float2 a23 = __half22float2(*(__half2*)&pv.y);
                    v = make_float4(a01.x, a01.y, a23.x, a23.y);
                } else {
                    v = Hf[idx];
                }
            } else v = make_float4(0.f, 0.f, 0.f, 0.f);
            if (use_act) {
                float4 sc = *(const float4*)(sScale + c);
                float4 sf = *(const float4*)(sShift + c);
                v.x = fmaxf(fmaf(v.x, sc.x, sf.x), 0.f);
                v.y = fmaxf(fmaf(v.y, sc.y, sf.y), 0.f);
                v.z = fmaxf(fmaf(v.z, sc.z, sf.z), 0.f);
                v.w = fmaxf(fmaf(v.w, sc.w, sf.w), 0.f);
            }
            __nv_bfloat162 h01 = __floats2bfloat162_rn(v.x, v.y);
            __nv_bfloat162 h23 = __floats2bfloat162_rn(v.z, v.w);
            float2 hf01 = __bfloat1622float2(h01);
            float2 hf23 = __bfloat1622float2(h23);
            __nv_bfloat162 l01 = __floats2bfloat162_rn(v.x - hf01.x, v.y - hf01.y);
            __nv_bfloat162 l23 = __floats2bfloat162_rn(v.z - hf23.x, v.w - hf23.y);
            uint32_t w0 = (uint32_t)(r * SA_W + (c >> 1));
            uint2 hh; hh.x = *(uint32_t*)&h01; hh.y = *(uint32_t*)&h23;
            uint2 ll; ll.x = *(uint32_t*)&l01; ll.y = *(uint32_t*)&l23;
            *(uint2*)(sm + SM_AHI + w0 * 4) = hh;
            *(uint2*)(sm + SM_ALO + w0 * 4) = ll;
        }
    }
    __syncthreads();

    const uint32_t* pAh = (const uint32_t*)(sm + SM_AHI);
    const uint32_t* pAl = (const uint32_t*)(sm + SM_ALO);
    const uint32_t* pBh = (const uint32_t*)(sm + SM_WHI);
    const uint32_t* pBl = (const uint32_t*)(sm + SM_WLO);

    int m0 = (wid & 3) * 16;
    int n0 = (wid >> 2) * 64;
    int gg = lane >> 2, q = lane & 3;

    float acc[8][4] = {};
#pragma unroll
    for (int k = 0; k < 8; k++) {
        int kb2 = k * 8;
        int ai = (m0 + gg) * SA_W + kb2 + q;
        uint32_t ah0 = pAh[ai],     ah1 = pAh[ai + 8 * SA_W];
        uint32_t ah2 = pAh[ai + 4], ah3 = pAh[ai + 8 * SA_W + 4];
        uint32_t al0 = pAl[ai],     al1 = pAl[ai + 8 * SA_W];
        uint32_t al2 = pAl[ai + 4], al3 = pAl[ai + 8 * SA_W + 4];
#pragma unroll
        for (int t = 0; t < 8; t++) {
            int bi = (n0 + t * 8 + gg) * SA_W + kb2 + q;
            uint32_t bh0 = pBh[bi], bh1 = pBh[bi + 4];
            uint32_t bl0 = pBl[bi], bl1 = pBl[bi + 4];
            mma_bf16(acc[t], ah0, ah1, ah2, ah3, bh0, bh1);
            mma_bf16(acc[t], al0, al1, al2, al3, bh0, bh1);
            mma_bf16(acc[t], ah0, ah1, ah2, ah3, bl0, bl1);
        }
    }

    int r0g = row0 + m0 + gg;
#pragma unroll
    for (int t = 0; t < 8; t++) {
        int colp = n0 + t * 8 + q * 2;
        float2 bv = *(const float2*)(bias + colp);
        if (r0g < N) {
            __half2 o = __floats2half2_rn(acc[t][0] + bv.x, acc[t][1] + bv.y);
            *(__half2*)(out + (size_t)r0g * D + colp) = o;
        }
        if (r0g + 8 < N) {
            __half2 o = __floats2half2_rn(acc[t][2] + bv.x, acc[t][3] + bv.y);
            *(__half2*)(out + (size_t)(r0g + 8) * D + colp) = o;
        }
    }
}

// ---------------- CSR build ----------------
__global__ void hist_kernel(const int* __restrict__ row, int* __restrict__ deg, int E)
{
    int e = blockIdx.x * blockDim.x + threadIdx.x;
    if (e < E) atomicAdd(&deg[row[e]], 1);
}

__global__ __launch_bounds__(1024) void blocksum_kernel(
    const int* __restrict__ deg, int* __restrict__ blksum, int N)
{
    int i = blockIdx.x * 1024 + threadIdx.x;
    int v = (i < N) ? deg[i] : 0;
#pragma unroll
    for (int off = 16; off > 0; off >>= 1) v += __shfl_down_sync(0xffffffffu, v, off);
    __shared__ int smr[32];
    int lane = threadIdx.x & 31, wid = threadIdx.x >> 5;
    if (lane == 0) smr[wid] = v;
    __syncthreads();
    if (wid == 0) {
        v = smr[lane];
#pragma unroll
        for (int off = 16; off > 0; off >>= 1) v += __shfl_down_sync(0xffffffffu, v, off);
        if (lane == 0) blksum[blockIdx.x] = v;
    }
}

__global__ __launch_bounds__(1024) void scanpart_kernel(int* __restrict__ blksum, int nb)
{
    __shared__ int smr[1024];
    int tid = threadIdx.x;
    smr[tid] = (tid < nb) ? blksum[tid] : 0;
    __syncthreads();
    if (tid == 0) {
        int run = 0;
        for (int i = 0; i < nb; i++) { int t = smr[i]; smr[i] = run; run += t; }
    }
    __syncthreads();
    if (tid < nb) blksum[tid] = smr[tid];
}

__global__ __launch_bounds__(1024) void rowptr_kernel(
    const int* __restrict__ deg, const int* __restrict__ blksum,
    int* __restrict__ rowptr, int* __restrict__ cursor, int N)
{
    int i = blockIdx.x * 1024 + threadIdx.x;
    int v = (i < N) ? deg[i] : 0;
    int lane = threadIdx.x & 31, wid = threadIdx.x >> 5;
    int incl = v;
#pragma unroll
    for (int off = 1; off < 32; off <<= 1) {
        int t = __shfl_up_sync(0xffffffffu, incl, off);
        if (lane >= off) incl += t;
    }
    __shared__ int wsum[32];
    if (lane == 31) wsum[wid] = incl;
    __syncthreads();
    if (wid == 0) {
        int w = wsum[lane];
#pragma unroll
        for (int off = 1; off < 32; off <<= 1) {
            int t = __shfl_up_sync(0xffffffffu, w, off);
            if (lane >= off) w += t;
        }
        wsum[lane] = w;
    }
    __syncthreads();
    int offset = blksum[blockIdx.x] + (wid > 0 ? wsum[wid - 1] : 0);
    int excl = offset + incl - v;
    if (i < N) { rowptr[i] = excl; cursor[i] = excl; }
    if (i == N - 1) rowptr[N] = excl + v;
}

__global__ void scatter_kernel(
    const int* __restrict__ row, const int* __restrict__ col,
    const float* __restrict__ ew, int* __restrict__ cursor,
    int2* __restrict__ edata, int E)
{
    int e = blockIdx.x * blockDim.x + threadIdx.x;
    if (e < E) {
        int p = atomicAdd(&cursor[row[e]], 1);
        int2 ed; ed.x = col[e]; ed.y = __float_as_int(ew[e]);
        edata[p] = ed;
    }
}

// ---------------- gather SpMM (fp16 in): fp16 out (outh) or fp32 out (outf) ------
__global__ __launch_bounds__(256) void spmm_kernel(
    const __half* __restrict__ H, const int* __restrict__ rowptr,
    const int2* __restrict__ edata,
    __half* __restrict__ outh, float* __restrict__ outf, int N)
{
    int r = blockIdx.x * 8 + (threadIdx.x >> 5);
    if (r >= N) return;
    int lane = threadIdx.x & 31;
    int start = rowptr[r], end = rowptr[r + 1];

    float4 acc = make_float4(0.f, 0.f, 0.f, 0.f);
    const uint2* Hv = (const uint2*)H;

    for (int base = start; base < end; base += 32) {
        int e = base + lane;
        int c = 0, wb = 0;
        if (e < end) { int2 ed = edata[e]; c = ed.x; wb = ed.y; }
        int cnt = min(32, end - base);
#pragma unroll 4
        for (int i = 0; i < cnt; i++) {
            int ci = __shfl_sync(0xffffffffu, c, i);
            float wi = __int_as_float(__shfl_sync(0xffffffffu, wb, i));
            uint2 pv = Hv[(size_t)ci * 32 + lane];
            float2 v01 = __half22float2(*(__half2*)&pv.x);
            float2 v23 = __half22float2(*(__half2*)&pv.y);
            acc.x = fmaf(wi, v01.x, acc.x);
            acc.y = fmaf(wi, v01.y, acc.y);
            acc.z = fmaf(wi, v23.x, acc.z);
            acc.w = fmaf(wi, v23.y, acc.w);
        }
    }
    if (outh) {
        __half2 o01 = __floats2half2_rn(acc.x, acc.y);
        __half2 o23 = __floats2half2_rn(acc.z, acc.w);
        uint2 st; st.x = *(uint32_t*)&o01; st.y = *(uint32_t*)&o23;
        ((uint2*)(outh + (size_t)r * D))[lane] = st;
    } else {
        ((float4*)(outf + (size_t)r * D))[lane] = acc;
    }
}

// ---------------- BN stats (reads fp16 A) ----------------
#define RPB 256
__global__ __launch_bounds__(128) void bn_stats_kernel(
    const __half* __restrict__ A, float* __restrict__ stats, int N)
{
    int d = threadIdx.x;
    int r0 = blockIdx.x * RPB;
    int rend = min(r0 + RPB, N);
    float s = 0.f, q = 0.f;
    for (int r = r0; r < rend; r++) {
        float v = __half2float(A[(size_t)r * D + d]);
        s += v;
        q = fmaf(v, v, q);
    }
    atomicAdd(&stats[d], s);
    atomicAdd(&stats[128 + d], q);
}

// ---------------------------------------------------------------------------
extern "C" void kernel_launch(void* const* d_in, const int* in_sizes, int n_in,
                              void* d_out, int out_size)
{
    const float* x   = (const float*)d_in[0];
    const float* ew  = (const float*)d_in[1];
    const float* W0  = (const float*)d_in[2];
    const float* b0  = (const float*)d_in[3];
    const float* g0  = (const float*)d_in[4];
    const float* be0 = (const float*)d_in[5];
    const float* W1  = (const float*)d_in[6];
    const float* b1  = (const float*)d_in[7];
    const float* g1  = (const float*)d_in[8];
    const float* be1 = (const float*)d_in[9];
    const float* W2  = (const float*)d_in[10];
    const float* b2  = (const float*)d_in[11];
    const int*   row = (const int*)d_in[12];
    const int*   col = (const int*)d_in[13];
    float* out = (float*)d_out;

    int N = in_sizes[0] / D;
    int E = in_sizes[1];

    float *Stats;
    __half *Z, *A;
    int *Deg, *Rowptr, *Cursor, *Blksum;
    int2* Edata;
    __nv_bfloat16 *Whi, *Wlo;
    cudaGetSymbolAddress((void**)&Z, g_Z);
    cudaGetSymbolAddress((void**)&A, g_A);
    cudaGetSymbolAddress((void**)&Stats, g_stats);
    cudaGetSymbolAddress((void**)&Deg, g_deg);
    cudaGetSymbolAddress((void**)&Rowptr, g_rowptr);
    cudaGetSymbolAddress((void**)&Cursor, g_cursor);
    cudaGetSymbolAddress((void**)&Edata, g_edata);
    cudaGetSymbolAddress((void**)&Blksum, g_blksum);
    cudaGetSymbolAddress((void**)&Whi, g_Whi);
    cudaGetSymbolAddress((void**)&Wlo, g_Wlo);

    cudaFuncSetAttribute(gemm_mma_kernel, cudaFuncAttributeMaxDynamicSharedMemorySize, SM_TOT);

    int gemmGrid  = (N + 63) / 64;
    int spmmGrid  = (N + 7) / 8;
    int statsGrid = (N + RPB - 1) / RPB;
    int nb        = (N + 1023) / 1024;
    float invN = 1.0f / (float)N;

    // ---- prep + CSR build (single stream, capture-safe) ----
    prep_kernel<<<16, 256>>>(W0, W1, W2, Whi, Wlo, Deg, Stats, N);
    hist_kernel<<<(E + 255) / 256, 256>>>(row, Deg, E);
    blocksum_kernel<<<nb, 1024>>>(Deg, Blksum, N);
    scanpart_kernel<<<1, 1024>>>(Blksum, nb);
    rowptr_kernel<<<nb, 1024>>>(Deg, Blksum, Rowptr, Cursor, N);
    scatter_kernel<<<(E + 255) / 256, 256>>>(row, col, ew, Cursor, Edata, E);

    // ---- layer 0 ----
    gemm_mma_kernel<<<gemmGrid, 256, SM_TOT>>>(x, 0, Whi, Wlo, b0,
                                               nullptr, nullptr, nullptr, Z, N, 0, invN);
    spmm_kernel<<<spmmGrid, 256>>>(Z, Rowptr, Edata, A, nullptr, N);
    bn_stats_kernel<<<statsGrid, 128>>>(A, Stats, N);

    // ---- layer 1 (applies BN0 fused) ----
    gemm_mma_kernel<<<gemmGrid, 256, SM_TOT>>>(A, 1, Whi + 128 * SA, Wlo + 128 * SA, b1,
                                               Stats, g0, be0, Z, N, 1, invN);
    spmm_kernel<<<spmmGrid, 256>>>(Z, Rowptr, Edata, A, nullptr, N);
    bn_stats_kernel<<<statsGrid, 128>>>(A, Stats + 256, N);

    // ---- layer 2 (applies BN1 fused; fp32 output to d_out) ----
    gemm_mma_kernel<<<gemmGrid, 256, SM_TOT>>>(A, 1, Whi + 256 * SA, Wlo + 256 * SA, b2,
                                               Stats + 256, g1, be1, Z, N, 1, invN);
    spmm_kernel<<<spmmGrid, 256>>>(Z, Rowptr, Edata, nullptr, out, N);
}

// round 13
// speedup vs baseline: 1.7963x; 1.3052x over previous
#include <cuda_runtime.h>
#include <cuda_fp16.h>
#include <cstdint>

#define D 128
#define EPS 1e-5f
#define MAXN 100000
#define MAXE 1600000
#define SA 136
#define SA_W (SA / 2)

__device__ __half g_Z[12800000];       // N x D fp16 (GEMM out / SpMM in)
__device__ __half g_A[12800000];       // N x D fp16 (SpMM out / stats + GEMM in)
__device__ float g_stats[4 * D];       // layer0: [0:256), layer1: [256:512)
__device__ int   g_deg[MAXN];
__device__ int   g_rowptr[MAXN + 1];
__device__ int   g_cursor[MAXN];
__device__ int2  g_edata[MAXE];
__device__ int   g_blksum[1024];
__device__ __half g_Wt[3 * 128 * SA];  // padded W^T fp16, 3 layers

// ---------------- prep: W transpose to fp16 padded + zero deg + zero stats ------
__global__ void prep_kernel(const float* __restrict__ W0, const float* __restrict__ W1,
                            const float* __restrict__ W2,
                            __half* __restrict__ wt,
                            int* __restrict__ deg, float* __restrict__ stats, int N)
{
    int b = blockIdx.x;
    if (b < 3) {
        const float* W = (b == 0) ? W0 : (b == 1) ? W1 : W2;
        __half* dst = wt + b * 128 * SA;
        for (int idx = threadIdx.x; idx < 16384; idx += blockDim.x) {
            int k = idx >> 7, n = idx & 127;     // W[k][n] -> Wt[n][k]
            dst[n * SA + k] = __float2half(W[idx]);
        }
    } else if (b == 3) {
        // 512 entries, 256 threads: two each (R9 lesson)
        stats[threadIdx.x]       = 0.f;
        stats[threadIdx.x + 256] = 0.f;
    } else {
        int per = (N + 11) / 12;
        int beg = (b - 4) * per;
        int end = min(beg + per, N);
        for (int i = beg + (int)threadIdx.x; i < end; i += blockDim.x) deg[i] = 0;
    }
}

// ---------------- fp16 HMMA GEMM with fused BN finalize + act ----------------
// H is fp32 (layer 0) or fp16 (layers 1/2) selected by h16 flag.
#define SM_A  0               // 64*136*2  = 17408
#define SM_W  17408           // 128*136*2 = 34816
#define SM_BN 52224           // scale[128] + shift[128]
#define SM_TOT 53248

__device__ __forceinline__ void mma_f16(float* c, uint32_t a0, uint32_t a1,
                                        uint32_t a2, uint32_t a3,
                                        uint32_t b0, uint32_t b1)
{
    asm volatile(
        "mma.sync.aligned.m16n8k16.row.col.f32.f16.f16.f32 "
        "{%0,%1,%2,%3}, {%4,%5,%6,%7}, {%8,%9}, {%0,%1,%2,%3};"
        : "+f"(c[0]), "+f"(c[1]), "+f"(c[2]), "+f"(c[3])
        : "r"(a0), "r"(a1), "r"(a2), "r"(a3), "r"(b0), "r"(b1));
}

__global__ __launch_bounds__(256) void gemm_mma_kernel(
    const void* __restrict__ Hp, int h16,
    const __half* __restrict__ wt,
    const float* __restrict__ bias,
    const float* __restrict__ stats,
    const float* __restrict__ gam, const float* __restrict__ bet,
    __half* __restrict__ out, int N, int use_act, float invN)
{
    extern __shared__ char sm[];
    int tid = threadIdx.x, wid = tid >> 5, lane = tid & 31;

    float* sScale = (float*)(sm + SM_BN);
    float* sShift = sScale + 128;

    // fused BN finalize: per-block scale/shift from raw stats
    if (use_act && tid < 128) {
        float m = stats[tid] * invN;
        float v = stats[128 + tid] * invN - m * m;
        float sc = gam[tid] * rsqrtf(v + EPS);
        sScale[tid] = sc;
        sShift[tid] = bet[tid] - m * sc;
    }

    // stage W (straight copy, already padded/transposed fp16): 2176 float4
    {
        const float4* bw = (const float4*)wt;
        float4* sw = (float4*)(sm + SM_W);
#pragma unroll
        for (int i = 0; i < 9; i++) {
            int idx = tid + 256 * i;
            if (idx < 2176) sw[idx] = bw[idx];
        }
    }
    __syncthreads();   // sScale/sShift ready before A staging

    // stage A tile: load H rows (fp32 or fp16), act, fp16 pack, padded store
    int row0 = blockIdx.x * 64;
    {
        const float4* Hf = (const float4*)Hp + (size_t)row0 * 32;
        const uint2*  Hh = (const uint2*)Hp + (size_t)row0 * 32;
#pragma unroll
        for (int i = 0; i < 8; i++) {
            int idx = tid + 256 * i;          // 2048 chunks of 4 elems
            int r = idx >> 5;
            int c = (idx & 31) * 4;
            float4 v;
            if (row0 + r < N) {
                if (h16) {
                    uint2 pv = Hh[idx];
                    float2 a01 = __half22float2(*(__half2*)&pv.x);
                    float2 a23 = __half22float2(*(__half2*)&pv.y);
                    v = make_float4(a01.x, a01.y, a23.x, a23.y);
                } else {
                    v = Hf[idx];
                }
            } else v = make_float4(0.f, 0.f, 0.f, 0.f);
            if (use_act) {
                float4 sc = *(const float4*)(sScale + c);
                float4 sf = *(const float4*)(sShift + c);
                v.x = fmaxf(fmaf(v.x, sc.x, sf.x), 0.f);
                v.y = fmaxf(fmaf(v.y, sc.y, sf.y), 0.f);
                v.z = fmaxf(fmaf(v.z, sc.z, sf.z), 0.f);
                v.w = fmaxf(fmaf(v.w, sc.w, sf.w), 0.f);
            }
            __half2 h01 = __floats2half2_rn(v.x, v.y);
            __half2 h23 = __floats2half2_rn(v.z, v.w);
            uint32_t w0 = (uint32_t)(r * SA_W + (c >> 1));
            uint2 hh; hh.x = *(uint32_t*)&h01; hh.y = *(uint32_t*)&h23;
            *(uint2*)(sm + SM_A + w0 * 4) = hh;
        }
    }
    __syncthreads();

    const uint32_t* pA = (const uint32_t*)(sm + SM_A);
    const uint32_t* pB = (const uint32_t*)(sm + SM_W);

    int m0 = (wid & 3) * 16;
    int n0 = (wid >> 2) * 64;
    int gg = lane >> 2, q = lane & 3;

    float acc[8][4] = {};
#pragma unroll
    for (int k = 0; k < 8; k++) {
        int kb2 = k * 8;
        int ai = (m0 + gg) * SA_W + kb2 + q;
        uint32_t a0 = pA[ai],     a1 = pA[ai + 8 * SA_W];
        uint32_t a2 = pA[ai + 4], a3 = pA[ai + 8 * SA_W + 4];
#pragma unroll
        for (int t = 0; t < 8; t++) {
            int bi = (n0 + t * 8 + gg) * SA_W + kb2 + q;
            mma_f16(acc[t], a0, a1, a2, a3, pB[bi], pB[bi + 4]);
        }
    }

    int r0g = row0 + m0 + gg;
#pragma unroll
    for (int t = 0; t < 8; t++) {
        int colp = n0 + t * 8 + q * 2;
        float2 bv = *(const float2*)(bias + colp);
        if (r0g < N) {
            __half2 o = __floats2half2_rn(acc[t][0] + bv.x, acc[t][1] + bv.y);
            *(__half2*)(out + (size_t)r0g * D + colp) = o;
        }
        if (r0g + 8 < N) {
            __half2 o = __floats2half2_rn(acc[t][2] + bv.x, acc[t][3] + bv.y);
            *(__half2*)(out + (size_t)(r0g + 8) * D + colp) = o;
        }
    }
}

// ---------------- CSR build ----------------
__global__ void hist_kernel(const int* __restrict__ row, int* __restrict__ deg, int E)
{
    int e = blockIdx.x * blockDim.x + threadIdx.x;
    if (e < E) atomicAdd(&deg[row[e]], 1);
}

__global__ __launch_bounds__(1024) void blocksum_kernel(
    const int* __restrict__ deg, int* __restrict__ blksum, int N)
{
    int i = blockIdx.x * 1024 + threadIdx.x;
    int v = (i < N) ? deg[i] : 0;
#pragma unroll
    for (int off = 16; off > 0; off >>= 1) v += __shfl_down_sync(0xffffffffu, v, off);
    __shared__ int smr[32];
    int lane = threadIdx.x & 31, wid = threadIdx.x >> 5;
    if (lane == 0) smr[wid] = v;
    __syncthreads();
    if (wid == 0) {
        v = smr[lane];
#pragma unroll
        for (int off = 16; off > 0; off >>= 1) v += __shfl_down_sync(0xffffffffu, v, off);
        if (lane == 0) blksum[blockIdx.x] = v;
    }
}

// rowptr: intra-block scan (warp 0 combines) + inter-block offset summed from raw
// blksum by warp 1 — no separate scanpart kernel.
__global__ __launch_bounds__(1024) void rowptr_kernel(
    const int* __restrict__ deg, const int* __restrict__ blksum,
    int* __restrict__ rowptr, int* __restrict__ cursor, int N)
{
    int i = blockIdx.x * 1024 + threadIdx.x;
    int v = (i < N) ? deg[i] : 0;
    int lane = threadIdx.x & 31, wid = threadIdx.x >> 5;
    int incl = v;
#pragma unroll
    for (int off = 1; off < 32; off <<= 1) {
        int t = __shfl_up_sync(0xffffffffu, incl, off);
        if (lane >= off) incl += t;
    }
    __shared__ int wsum[32];
    __shared__ int s_base;
    if (lane == 31) wsum[wid] = incl;
    __syncthreads();
    if (wid == 0) {
        int w = wsum[lane];
#pragma unroll
        for (int off = 1; off < 32; off <<= 1) {
            int t = __shfl_up_sync(0xffffffffu, w, off);
            if (lane >= off) w += t;
        }
        wsum[lane] = w;
    } else if (wid == 1) {
        int accb = 0;
        for (int j = lane; j < (int)blockIdx.x; j += 32) accb += blksum[j];
#pragma unroll
        for (int off = 16; off > 0; off >>= 1)
            accb += __shfl_down_sync(0xffffffffu, accb, off);
        if (lane == 0) s_base = accb;
    }
    __syncthreads();
    int offset = s_base + (wid > 0 ? wsum[wid - 1] : 0);
    int excl = offset + incl - v;
    if (i < N) { rowptr[i] = excl; cursor[i] = excl; }
    if (i == N - 1) rowptr[N] = excl + v;
}

__global__ void scatter_kernel(
    const int* __restrict__ row, const int* __restrict__ col,
    const float* __restrict__ ew, int* __restrict__ cursor,
    int2* __restrict__ edata, int E)
{
    int e = blockIdx.x * blockDim.x + threadIdx.x;
    if (e < E) {
        int p = atomicAdd(&cursor[row[e]], 1);
        int2 ed; ed.x = col[e]; ed.y = __float_as_int(ew[e]);
        edata[p] = ed;
    }
}

// ---------------- gather SpMM (fp16 in): fp16 out (outh) or fp32 out (outf) ------
__global__ __launch_bounds__(256) void spmm_kernel(
    const __half* __restrict__ H, const int* __restrict__ rowptr,
    const int2* __restrict__ edata,
    __half* __restrict__ outh, float* __restrict__ outf, int N)
{
    int r = blockIdx.x * 8 + (threadIdx.x >> 5);
    if (r >= N) return;
    int lane = threadIdx.x & 31;
    int start = rowptr[r], end = rowptr[r + 1];

    float4 acc = make_float4(0.f, 0.f, 0.f, 0.f);
    const uint2* Hv = (const uint2*)H;

    for (int base = start; base < end; base += 32) {
        int e = base + lane;
        int c = 0, wb = 0;
        if (e < end) { int2 ed = edata[e]; c = ed.x; wb = ed.y; }
        int cnt = min(32, end - base);
#pragma unroll 8
        for (int i = 0; i < cnt; i++) {
            int ci = __shfl_sync(0xffffffffu, c, i);
            float wi = __int_as_float(__shfl_sync(0xffffffffu, wb, i));
            uint2 pv = Hv[(size_t)ci * 32 + lane];
            float2 v01 = __half22float2(*(__half2*)&pv.x);
            float2 v23 = __half22float2(*(__half2*)&pv.y);
            acc.x = fmaf(wi, v01.x, acc.x);
            acc.y = fmaf(wi, v01.y, acc.y);
            acc.z = fmaf(wi, v23.x, acc.z);
            acc.w = fmaf(wi, v23.y, acc.w);
        }
    }
    if (outh) {
        __half2 o01 = __floats2half2_rn(acc.x, acc.y);
        __half2 o23 = __floats2half2_rn(acc.z, acc.w);
        uint2 st; st.x = *(uint32_t*)&o01; st.y = *(uint32_t*)&o23;
        ((uint2*)(outh + (size_t)r * D))[lane] = st;
    } else {
        ((float4*)(outf + (size_t)r * D))[lane] = acc;
    }
}

// ---------------- BN stats (reads fp16 A) ----------------
#define RPB 256
__global__ __launch_bounds__(128) void bn_stats_kernel(
    const __half* __restrict__ A, float* __restrict__ stats, int N)
{
    int d = threadIdx.x;
    int r0 = blockIdx.x * RPB;
    int rend = min(r0 + RPB, N);
    float s = 0.f, q = 0.f;
    for (int r = r0; r < rend; r++) {
        float v = __half2float(A[(size_t)r * D + d]);
        s += v;
        q = fmaf(v, v, q);
    }
    atomicAdd(&stats[d], s);
    atomicAdd(&stats[128 + d], q);
}

// ---------------------------------------------------------------------------
extern "C" void kernel_launch(void* const* d_in, const int* in_sizes, int n_in,
                              void* d_out, int out_size)
{
    const float* x   = (const float*)d_in[0];
    const float* ew  = (const float*)d_in[1];
    const float* W0  = (const float*)d_in[2];
    const float* b0  = (const float*)d_in[3];
    const float* g0  = (const float*)d_in[4];
    const float* be0 = (const float*)d_in[5];
    const float* W1  = (const float*)d_in[6];
    const float* b1  = (const float*)d_in[7];
    const float* g1  = (const float*)d_in[8];
    const float* be1 = (const float*)d_in[9];
    const float* W2  = (const float*)d_in[10];
    const float* b2  = (const float*)d_in[11];
    const int*   row = (const int*)d_in[12];
    const int*   col = (const int*)d_in[13];
    float* out = (float*)d_out;

    int N = in_sizes[0] / D;
    int E = in_sizes[1];

    float *Stats;
    __half *Z, *A, *Wt;
    int *Deg, *Rowptr, *Cursor, *Blksum;
    int2* Edata;
    cudaGetSymbolAddress((void**)&Z, g_Z);
    cudaGetSymbolAddress((void**)&A, g_A);
    cudaGetSymbolAddress((void**)&Stats, g_stats);
    cudaGetSymbolAddress((void**)&Deg, g_deg);
    cudaGetSymbolAddress((void**)&Rowptr, g_rowptr);
    cudaGetSymbolAddress((void**)&Cursor, g_cursor);
    cudaGetSymbolAddress((void**)&Edata, g_edata);
    cudaGetSymbolAddress((void**)&Blksum, g_blksum);
    cudaGetSymbolAddress((void**)&Wt, g_Wt);

    cudaFuncSetAttribute(gemm_mma_kernel, cudaFuncAttributeMaxDynamicSharedMemorySize, SM_TOT);

    int gemmGrid  = (N + 63) / 64;
    int spmmGrid  = (N + 7) / 8;
    int statsGrid = (N + RPB - 1) / RPB;
    int nb        = (N + 1023) / 1024;
    float invN = 1.0f / (float)N;

    // ---- prep + CSR build (single stream) ----
    prep_kernel<<<16, 256>>>(W0, W1, W2, Wt, Deg, Stats, N);
    hist_kernel<<<(E + 255) / 256, 256>>>(row, Deg, E);
    blocksum_kernel<<<nb, 1024>>>(Deg, Blksum, N);
    rowptr_kernel<<<nb, 1024>>>(Deg, Blksum, Rowptr, Cursor, N);
    scatter_kernel<<<(E + 255) / 256, 256>>>(row, col, ew, Cursor, Edata, E);

    // ---- layer 0 ----
    gemm_mma_kernel<<<gemmGrid, 256, SM_TOT>>>(x, 0, Wt, b0,
                                               nullptr, nullptr, nullptr, Z, N, 0, invN);
    spmm_kernel<<<spmmGrid, 256>>>(Z, Rowptr, Edata, A, nullptr, N);
    bn_stats_kernel<<<statsGrid, 128>>>(A, Stats, N);

    // ---- layer 1 (applies BN0 fused) ----
    gemm_mma_kernel<<<gemmGrid, 256, SM_TOT>>>(A, 1, Wt + 128 * SA, b1,
                                               Stats, g0, be0, Z, N, 1, invN);
    spmm_kernel<<<spmmGrid, 256>>>(Z, Rowptr, Edata, A, nullptr, N);
    bn_stats_kernel<<<statsGrid, 128>>>(A, Stats + 256, N);

    // ---- layer 2 (applies BN1 fused; fp32 output to d_out) ----
    gemm_mma_kernel<<<gemmGrid, 256, SM_TOT>>>(A, 1, Wt + 256 * SA, b2,
                                               Stats + 256, g1, be1, Z, N, 1, invN);
    spmm_kernel<<<spmmGrid, 256>>>(Z, Rowptr, Edata, nullptr, out, N);
}